// round 7
// baseline (speedup 1.0000x reference)
#include <cuda_runtime.h>
#include <cstdint>

// ChamferLoss: B=4, C=3, N=M=8192
// loss = 2/B * sum_{b,n} max( min_m ||q_bn - r_bm||^2 , 0 )
//
// Ref set split into 2 halves -> 64KB smem/block -> 2 CTAs/SM -> 2 warps/SMSP.
// Each block writes per-query unclamped partial (q2 + min_t) for its half;
// finalize kernel min-combines halves, clamps, sums, scales.

#define BATCH     4
#define NPTS      8192
#define NHALF     (NPTS / 2)          // 4096 ref points per half
#define NPAIRS_B  (NHALF / 2)         // 2048 pairs per block
#define TPB       128
#define QPT       2
#define QPB       (TPB * QPT)         // 256 queries per block
#define QBLOCKS   (NPTS / QPB)        // 32
#define NBLOCKS   (BATCH * QBLOCKS * 2)  // 256 (x2 ref halves)
#define SMEM_BYTES (NPAIRS_B * 32)    // 64 KB
#define BN        (BATCH * NPTS)      // 32768

__device__ float g_min[2 * BN];       // [half][b*NPTS + n], unclamped q2+min

__device__ __forceinline__ uint64_t pk2(float lo, float hi) {
    uint64_t r;
    asm("mov.b64 %0, {%1, %2};" : "=l"(r) : "f"(lo), "f"(hi));
    return r;
}
__device__ __forceinline__ uint64_t fma_f32x2(uint64_t a, uint64_t b, uint64_t c) {
    uint64_t d;
    asm("fma.rn.f32x2 %0, %1, %2, %3;" : "=l"(d) : "l"(a), "l"(b), "l"(c));
    return d;
}
__device__ __forceinline__ float2 upk2(uint64_t v) {
    float2 r;
    asm("mov.b64 {%0, %1}, %2;" : "=f"(r.x), "=f"(r.y) : "l"(v));
    return r;
}

// One ref-pair body at immediate smem byte offset OFF from 'addr'.
#define PAIR_BODY(OFF)                                                          \
    {                                                                           \
        uint64_t X, Y, Z, W;                                                    \
        asm volatile("ld.shared.v2.b64 {%0,%1}, [%2+" #OFF "];"                 \
                     : "=l"(X), "=l"(Y) : "r"(addr));                           \
        asm volatile("ld.shared.v2.b64 {%0,%1}, [%2+" #OFF "+16];"              \
                     : "=l"(Z), "=l"(W) : "r"(addr));                           \
        uint64_t ta = fma_f32x2(QXA, X, fma_f32x2(QYA, Y, fma_f32x2(QZA, Z, W)));\
        uint64_t tb = fma_f32x2(QXB, X, fma_f32x2(QYB, Y, fma_f32x2(QZB, Z, W)));\
        float2 fa = upk2(ta);                                                   \
        float2 fb = upk2(tb);                                                   \
        ma0 = fminf(ma0, fa.x);                                                 \
        ma1 = fminf(ma1, fa.y);                                                 \
        mb0 = fminf(mb0, fb.x);                                                 \
        mb1 = fminf(mb1, fb.y);                                                 \
    }

__global__ void __launch_bounds__(TPB)
chamfer_min_kernel(const float* __restrict__ pc2,
                   const float* __restrict__ pc1w)
{
    extern __shared__ float4 s[];  // [2*NPAIRS_B]

    // blockIdx.x = ((b*QBLOCKS)+qb)*2 + h
    const int h  = blockIdx.x & 1;
    const int bq = blockIdx.x >> 1;
    const int b  = bq / QBLOCKS;
    const int qb = bq % QBLOCKS;

    // Stage this half's ref points, pre-scaled and pair-packed.
    const float* __restrict__ rp = pc1w + (size_t)b * 3 * NPTS + h * NHALF;
    for (int p = threadIdx.x; p < NPAIRS_B; p += TPB) {
        float x0 = rp[2 * p],            x1 = rp[2 * p + 1];
        float y0 = rp[NPTS + 2 * p],     y1 = rp[NPTS + 2 * p + 1];
        float z0 = rp[2 * NPTS + 2 * p], z1 = rp[2 * NPTS + 2 * p + 1];
        float w0 = fmaf(x0, x0, fmaf(y0, y0, z0 * z0));
        float w1 = fmaf(x1, x1, fmaf(y1, y1, z1 * z1));
        s[2 * p]     = make_float4(-2.0f * x0, -2.0f * x1, -2.0f * y0, -2.0f * y1);
        s[2 * p + 1] = make_float4(-2.0f * z0, -2.0f * z1, w0, w1);
    }
    __syncthreads();

    // Two query points per thread.
    const int na = qb * QPB + threadIdx.x;
    const int nb = na + TPB;
    const float* __restrict__ qp = pc2 + (size_t)b * 3 * NPTS;
    const float qxa = qp[na], qya = qp[NPTS + na], qza = qp[2 * NPTS + na];
    const float qxb = qp[nb], qyb = qp[NPTS + nb], qzb = qp[2 * NPTS + nb];
    const float q2a = fmaf(qxa, qxa, fmaf(qya, qya, qza * qza));
    const float q2b = fmaf(qxb, qxb, fmaf(qyb, qyb, qzb * qzb));

    const uint64_t QXA = pk2(qxa, qxa), QYA = pk2(qya, qya), QZA = pk2(qza, qza);
    const uint64_t QXB = pk2(qxb, qxb), QYB = pk2(qyb, qyb), QZB = pk2(qzb, qzb);

    float ma0 = 3.4e38f, ma1 = 3.4e38f;
    float mb0 = 3.4e38f, mb1 = 3.4e38f;

    uint32_t addr = (uint32_t)__cvta_generic_to_shared(s);

    #pragma unroll 1
    for (int p = 0; p < NPAIRS_B; p += 8) {
        PAIR_BODY(0)
        PAIR_BODY(32)
        PAIR_BODY(64)
        PAIR_BODY(96)
        PAIR_BODY(128)
        PAIR_BODY(160)
        PAIR_BODY(192)
        PAIR_BODY(224)
        addr += 8 * 32;
    }

    // Unclamped per-query partial for this ref half.
    float* dst = g_min + h * BN + b * NPTS;
    dst[na] = q2a + fminf(ma0, ma1);
    dst[nb] = q2b + fminf(mb0, mb1);
}

#define FTPB 1024

__global__ void __launch_bounds__(FTPB)
chamfer_finalize_kernel(float* __restrict__ out)
{
    float acc = 0.0f;
    // Deterministic per-thread order; coalesced across threads.
    for (int i = threadIdx.x; i < BN; i += FTPB) {
        float v = fminf(g_min[i], g_min[BN + i]);
        acc += fmaxf(v, 0.0f);
    }
    __shared__ float red[FTPB];
    red[threadIdx.x] = acc;
    __syncthreads();
    #pragma unroll
    for (int sH = FTPB / 2; sH > 0; sH >>= 1) {
        if (threadIdx.x < sH) red[threadIdx.x] += red[threadIdx.x + sH];
        __syncthreads();
    }
    if (threadIdx.x == 0) {
        out[0] = red[0] * (2.0f / (float)BATCH);  // 2 * mean over batches
    }
}

extern "C" void kernel_launch(void* const* d_in, const int* in_sizes, int n_in,
                              void* d_out, int out_size)
{
    const float* pc2  = (const float*)d_in[0];
    const float* pc1w = (const float*)d_in[1];
    float* out = (float*)d_out;

    cudaFuncSetAttribute(chamfer_min_kernel,
                         cudaFuncAttributeMaxDynamicSharedMemorySize,
                         SMEM_BYTES);

    chamfer_min_kernel<<<NBLOCKS, TPB, SMEM_BYTES>>>(pc2, pc1w);
    chamfer_finalize_kernel<<<1, FTPB>>>(out);
}

// round 8
// speedup vs baseline: 1.2206x; 1.2206x over previous
#include <cuda_runtime.h>
#include <cstdint>

// ChamferLoss: B=4, C=3, N=M=8192
// loss = 2/B * sum_{b,n} max( min_m ||q_bn - r_bm||^2 , 0 )
//
// Refs split into 4 quarters (32KB smem/CTA -> 2 CTAs/SM -> 4 warps/SMSP).
// Each block: 512 queries (2/thread) vs one 2048-pt ref quarter, f32x2 FMAs.
// Per-query unclamped partials (q2 + min_t) -> g_min[quarter][b*N+n].
// Last-arriving block min-combines quarters, clamps, sums (fixed order), scales.

#define BATCH     4
#define NPTS      8192
#define NQUART    (NPTS / 4)          // 2048 ref points per quarter
#define NPAIRS_B  (NQUART / 2)        // 1024 pairs per block
#define TPB       256
#define QPT       2
#define QPB       (TPB * QPT)         // 512 queries per block
#define QBLOCKS   (NPTS / QPB)        // 16
#define NBLOCKS   (BATCH * QBLOCKS * 4)  // 256
#define SMEM_BYTES (NPAIRS_B * 32)    // 32 KB
#define BN        (BATCH * NPTS)      // 32768

__device__ float g_min[4 * BN];
__device__ int   g_count = 0;

__device__ __forceinline__ uint64_t pk2(float lo, float hi) {
    uint64_t r;
    asm("mov.b64 %0, {%1, %2};" : "=l"(r) : "f"(lo), "f"(hi));
    return r;
}
__device__ __forceinline__ uint64_t fma_f32x2(uint64_t a, uint64_t b, uint64_t c) {
    uint64_t d;
    asm("fma.rn.f32x2 %0, %1, %2, %3;" : "=l"(d) : "l"(a), "l"(b), "l"(c));
    return d;
}
__device__ __forceinline__ float2 upk2(uint64_t v) {
    float2 r;
    asm("mov.b64 {%0, %1}, %2;" : "=f"(r.x), "=f"(r.y) : "l"(v));
    return r;
}

#define PAIR_BODY(OFF)                                                          \
    {                                                                           \
        uint64_t X, Y, Z, W;                                                    \
        asm volatile("ld.shared.v2.b64 {%0,%1}, [%2+" #OFF "];"                 \
                     : "=l"(X), "=l"(Y) : "r"(addr));                           \
        asm volatile("ld.shared.v2.b64 {%0,%1}, [%2+" #OFF "+16];"              \
                     : "=l"(Z), "=l"(W) : "r"(addr));                           \
        uint64_t ta = fma_f32x2(QXA, X, fma_f32x2(QYA, Y, fma_f32x2(QZA, Z, W)));\
        uint64_t tb = fma_f32x2(QXB, X, fma_f32x2(QYB, Y, fma_f32x2(QZB, Z, W)));\
        float2 fa = upk2(ta);                                                   \
        float2 fb = upk2(tb);                                                   \
        ma0 = fminf(ma0, fa.x);                                                 \
        ma1 = fminf(ma1, fa.y);                                                 \
        mb0 = fminf(mb0, fb.x);                                                 \
        mb1 = fminf(mb1, fb.y);                                                 \
    }

__global__ void __launch_bounds__(TPB, 2)
chamfer_kernel(const float* __restrict__ pc2,
               const float* __restrict__ pc1w,
               float* __restrict__ out)
{
    extern __shared__ float4 s[];  // [2*NPAIRS_B]

    // blockIdx.x = ((b*QBLOCKS)+qb)*4 + quarter
    const int qt = blockIdx.x & 3;
    const int bq = blockIdx.x >> 2;
    const int b  = bq / QBLOCKS;
    const int qb = bq % QBLOCKS;

    // Stage this quarter's ref points, pre-scaled (-2x,-2y,-2z, |r|^2), pair-packed.
    const float* __restrict__ rp = pc1w + (size_t)b * 3 * NPTS + qt * NQUART;
    for (int p = threadIdx.x; p < NPAIRS_B; p += TPB) {
        float x0 = rp[2 * p],            x1 = rp[2 * p + 1];
        float y0 = rp[NPTS + 2 * p],     y1 = rp[NPTS + 2 * p + 1];
        float z0 = rp[2 * NPTS + 2 * p], z1 = rp[2 * NPTS + 2 * p + 1];
        float w0 = fmaf(x0, x0, fmaf(y0, y0, z0 * z0));
        float w1 = fmaf(x1, x1, fmaf(y1, y1, z1 * z1));
        s[2 * p]     = make_float4(-2.0f * x0, -2.0f * x1, -2.0f * y0, -2.0f * y1);
        s[2 * p + 1] = make_float4(-2.0f * z0, -2.0f * z1, w0, w1);
    }
    __syncthreads();

    // Two query points per thread.
    const int na = qb * QPB + threadIdx.x;
    const int nb = na + TPB;
    const float* __restrict__ qp = pc2 + (size_t)b * 3 * NPTS;
    const float qxa = qp[na], qya = qp[NPTS + na], qza = qp[2 * NPTS + na];
    const float qxb = qp[nb], qyb = qp[NPTS + nb], qzb = qp[2 * NPTS + nb];
    const float q2a = fmaf(qxa, qxa, fmaf(qya, qya, qza * qza));
    const float q2b = fmaf(qxb, qxb, fmaf(qyb, qyb, qzb * qzb));

    const uint64_t QXA = pk2(qxa, qxa), QYA = pk2(qya, qya), QZA = pk2(qza, qza);
    const uint64_t QXB = pk2(qxb, qxb), QYB = pk2(qyb, qyb), QZB = pk2(qzb, qzb);

    float ma0 = 3.4e38f, ma1 = 3.4e38f;
    float mb0 = 3.4e38f, mb1 = 3.4e38f;

    uint32_t addr = (uint32_t)__cvta_generic_to_shared(s);

    #pragma unroll 1
    for (int p = 0; p < NPAIRS_B; p += 4) {
        PAIR_BODY(0)
        PAIR_BODY(32)
        PAIR_BODY(64)
        PAIR_BODY(96)
        addr += 4 * 32;
    }

    // Per-query unclamped partial for this quarter.
    float* dst = g_min + qt * BN + b * NPTS;
    dst[na] = q2a + fminf(ma0, ma1);
    dst[nb] = q2b + fminf(mb0, mb1);

    // ---- last-block finalize ----
    __shared__ int is_last;
    __threadfence();
    __syncthreads();
    if (threadIdx.x == 0) {
        int old = atomicAdd(&g_count, 1);
        is_last = (old == NBLOCKS - 1);
    }
    __syncthreads();

    if (is_last) {
        __threadfence();
        const float4* q0 = (const float4*)(g_min);
        const float4* q1 = (const float4*)(g_min + BN);
        const float4* q2v = (const float4*)(g_min + 2 * BN);
        const float4* q3 = (const float4*)(g_min + 3 * BN);

        float acc = 0.0f;
        // Fixed per-thread order -> deterministic final sum.
        for (int i = threadIdx.x; i < BN / 4; i += TPB) {
            float4 a = q0[i], c = q1[i], d = q2v[i], e = q3[i];
            acc += fmaxf(fminf(fminf(a.x, c.x), fminf(d.x, e.x)), 0.0f);
            acc += fmaxf(fminf(fminf(a.y, c.y), fminf(d.y, e.y)), 0.0f);
            acc += fmaxf(fminf(fminf(a.z, c.z), fminf(d.z, e.z)), 0.0f);
            acc += fmaxf(fminf(fminf(a.w, c.w), fminf(d.w, e.w)), 0.0f);
        }
        __shared__ float red[TPB];
        red[threadIdx.x] = acc;
        __syncthreads();
        #pragma unroll
        for (int sH = TPB / 2; sH > 0; sH >>= 1) {
            if (threadIdx.x < sH) red[threadIdx.x] += red[threadIdx.x + sH];
            __syncthreads();
        }
        if (threadIdx.x == 0) {
            out[0] = red[0] * (2.0f / (float)BATCH);  // 2 * mean over batches
            g_count = 0;                               // reset for next replay
        }
    }
}

extern "C" void kernel_launch(void* const* d_in, const int* in_sizes, int n_in,
                              void* d_out, int out_size)
{
    const float* pc2  = (const float*)d_in[0];
    const float* pc1w = (const float*)d_in[1];
    float* out = (float*)d_out;

    cudaFuncSetAttribute(chamfer_kernel,
                         cudaFuncAttributeMaxDynamicSharedMemorySize,
                         SMEM_BYTES);

    chamfer_kernel<<<NBLOCKS, TPB, SMEM_BYTES>>>(pc2, pc1w, out);
}

// round 10
// speedup vs baseline: 1.4207x; 1.1640x over previous
#include <cuda_runtime.h>
#include <cstdint>

// ChamferLoss: B=4, C=3, N=M=8192
// loss = 2/B * sum_{b,n} max( min_m ||q_bn - r_bm||^2 , 0 )
//
// Refs split into 4 quarters (32KB smem/CTA -> 2 CTAs/SM -> 4 warps/SMSP).
// 512 queries/block (2 per thread) vs one 2048-pt ref quarter.
// f32x2 packed FMAs (2 ref pts / instr), software-pipelined smem loads
// (double-buffered register chunks, non-volatile -> scheduler freedom).
// Per-query unclamped partials -> g_min[quarter][]; last block finalizes.

#define BATCH     4
#define NPTS      8192
#define NQUART    (NPTS / 4)          // 2048 ref points per quarter
#define NPAIRS_B  (NQUART / 2)        // 1024 pairs per block
#define TPB       256
#define QPT       2
#define QPB       (TPB * QPT)         // 512 queries per block
#define QBLOCKS   (NPTS / QPB)        // 16
#define NBLOCKS   (BATCH * QBLOCKS * 4)  // 256
#define CHUNK     4                   // pairs per pipeline stage
#define SMEM_BYTES      (NPAIRS_B * 32)
#define SMEM_BYTES_PAD  (SMEM_BYTES + CHUNK * 32)   // +1 sentinel chunk
#define BN        (BATCH * NPTS)      // 32768

__device__ float g_min[4 * BN];
__device__ int   g_count = 0;

__device__ __forceinline__ uint64_t pk2(float lo, float hi) {
    uint64_t r;
    asm("mov.b64 %0, {%1, %2};" : "=l"(r) : "f"(lo), "f"(hi));
    return r;
}
__device__ __forceinline__ uint64_t fma_f32x2(uint64_t a, uint64_t b, uint64_t c) {
    uint64_t d;
    asm("fma.rn.f32x2 %0, %1, %2, %3;" : "=l"(d) : "l"(a), "l"(b), "l"(c));
    return d;
}
__device__ __forceinline__ float2 upk2(uint64_t v) {
    float2 r;
    asm("mov.b64 {%0, %1}, %2;" : "=f"(r.x), "=f"(r.y) : "l"(v));
    return r;
}

struct Chunk {
    uint64_t X[CHUNK], Y[CHUNK], Z[CHUNK], W[CHUNK];
};

__device__ __forceinline__ void load_chunk(const char* sb, int off, Chunk& c) {
    #pragma unroll
    for (int u = 0; u < CHUNK; u++) {
        ulonglong2 a = *(const ulonglong2*)(sb + off + u * 32);      // (-2x01,-2y01)
        ulonglong2 b = *(const ulonglong2*)(sb + off + u * 32 + 16); // (-2z01, w01)
        c.X[u] = a.x; c.Y[u] = a.y; c.Z[u] = b.x; c.W[u] = b.y;
    }
}

#define COMPUTE_CHUNK(C)                                                        \
    {                                                                           \
        _Pragma("unroll")                                                       \
        for (int u = 0; u < CHUNK; u++) {                                       \
            uint64_t ta = fma_f32x2(QXA, (C).X[u],                              \
                           fma_f32x2(QYA, (C).Y[u],                             \
                            fma_f32x2(QZA, (C).Z[u], (C).W[u])));               \
            uint64_t tb = fma_f32x2(QXB, (C).X[u],                              \
                           fma_f32x2(QYB, (C).Y[u],                             \
                            fma_f32x2(QZB, (C).Z[u], (C).W[u])));               \
            float2 fa = upk2(ta);                                               \
            float2 fb = upk2(tb);                                               \
            ma0 = fminf(ma0, fa.x);                                             \
            ma1 = fminf(ma1, fa.y);                                             \
            mb0 = fminf(mb0, fb.x);                                             \
            mb1 = fminf(mb1, fb.y);                                             \
        }                                                                       \
    }

__global__ void __launch_bounds__(TPB, 2)
chamfer_kernel(const float* __restrict__ pc2,
               const float* __restrict__ pc1w,
               float* __restrict__ out)
{
    extern __shared__ float4 s[];  // [2*(NPAIRS_B+CHUNK)]

    // blockIdx.x = ((b*QBLOCKS)+qb)*4 + quarter
    const int qt = blockIdx.x & 3;
    const int bq = blockIdx.x >> 2;
    const int b  = bq / QBLOCKS;
    const int qb = bq % QBLOCKS;

    // Stage this quarter's refs, pre-scaled (-2x,-2y,-2z,|r|^2), pair-packed.
    const float* __restrict__ rp = pc1w + (size_t)b * 3 * NPTS + qt * NQUART;
    for (int p = threadIdx.x; p < NPAIRS_B; p += TPB) {
        float x0 = rp[2 * p],            x1 = rp[2 * p + 1];
        float y0 = rp[NPTS + 2 * p],     y1 = rp[NPTS + 2 * p + 1];
        float z0 = rp[2 * NPTS + 2 * p], z1 = rp[2 * NPTS + 2 * p + 1];
        float w0 = fmaf(x0, x0, fmaf(y0, y0, z0 * z0));
        float w1 = fmaf(x1, x1, fmaf(y1, y1, z1 * z1));
        s[2 * p]     = make_float4(-2.0f * x0, -2.0f * x1, -2.0f * y0, -2.0f * y1);
        s[2 * p + 1] = make_float4(-2.0f * z0, -2.0f * z1, w0, w1);
    }
    // Sentinel pad chunk: never wins the min (w = +huge).
    if (threadIdx.x < CHUNK) {
        s[2 * (NPAIRS_B + threadIdx.x)]     = make_float4(0.f, 0.f, 0.f, 0.f);
        s[2 * (NPAIRS_B + threadIdx.x) + 1] = make_float4(0.f, 0.f, 3.4e38f, 3.4e38f);
    }
    __syncthreads();

    // Two query points per thread.
    const int na = qb * QPB + threadIdx.x;
    const int nb = na + TPB;
    const float* __restrict__ qp = pc2 + (size_t)b * 3 * NPTS;
    const float qxa = qp[na], qya = qp[NPTS + na], qza = qp[2 * NPTS + na];
    const float qxb = qp[nb], qyb = qp[NPTS + nb], qzb = qp[2 * NPTS + nb];
    const float q2a = fmaf(qxa, qxa, fmaf(qya, qya, qza * qza));
    const float q2b = fmaf(qxb, qxb, fmaf(qyb, qyb, qzb * qzb));

    const uint64_t QXA = pk2(qxa, qxa), QYA = pk2(qya, qya), QZA = pk2(qza, qza);
    const uint64_t QXB = pk2(qxb, qxb), QYB = pk2(qyb, qyb), QZB = pk2(qzb, qzb);

    float ma0 = 3.4e38f, ma1 = 3.4e38f;
    float mb0 = 3.4e38f, mb1 = 3.4e38f;

    const char* sb = (const char*)s;
    Chunk A, B;
    load_chunk(sb, 0, A);

    // Software pipeline: loads always one chunk ahead of compute.
    int off = 0;
    #pragma unroll 1
    for (int p = 0; p < NPAIRS_B; p += 2 * CHUNK) {
        load_chunk(sb, off + CHUNK * 32, B);
        COMPUTE_CHUNK(A)
        load_chunk(sb, off + 2 * CHUNK * 32, A);  // final iter reads sentinel pad
        COMPUTE_CHUNK(B)
        off += 2 * CHUNK * 32;
    }

    // Per-query unclamped partial for this quarter.
    float* dst = g_min + qt * BN + b * NPTS;
    dst[na] = q2a + fminf(ma0, ma1);
    dst[nb] = q2b + fminf(mb0, mb1);

    // ---- last-block finalize ----
    __shared__ int is_last;
    __threadfence();
    __syncthreads();
    if (threadIdx.x == 0) {
        int old = atomicAdd(&g_count, 1);
        is_last = (old == NBLOCKS - 1);
    }
    __syncthreads();

    if (is_last) {
        __threadfence();
        const float4* q0 = (const float4*)(g_min);
        const float4* q1 = (const float4*)(g_min + BN);
        const float4* q2v = (const float4*)(g_min + 2 * BN);
        const float4* q3 = (const float4*)(g_min + 3 * BN);

        float acc = 0.0f;
        for (int i = threadIdx.x; i < BN / 4; i += TPB) {
            float4 a = q0[i], c = q1[i], d = q2v[i], e = q3[i];
            acc += fmaxf(fminf(fminf(a.x, c.x), fminf(d.x, e.x)), 0.0f);
            acc += fmaxf(fminf(fminf(a.y, c.y), fminf(d.y, e.y)), 0.0f);
            acc += fmaxf(fminf(fminf(a.z, c.z), fminf(d.z, e.z)), 0.0f);
            acc += fmaxf(fminf(fminf(a.w, c.w), fminf(d.w, e.w)), 0.0f);
        }
        __shared__ float red[TPB];
        red[threadIdx.x] = acc;
        __syncthreads();
        #pragma unroll
        for (int sH = TPB / 2; sH > 0; sH >>= 1) {
            if (threadIdx.x < sH) red[threadIdx.x] += red[threadIdx.x + sH];
            __syncthreads();
        }
        if (threadIdx.x == 0) {
            out[0] = red[0] * (2.0f / (float)BATCH);  // 2 * mean over batches
            g_count = 0;                               // reset for next replay
        }
    }
}

extern "C" void kernel_launch(void* const* d_in, const int* in_sizes, int n_in,
                              void* d_out, int out_size)
{
    const float* pc2  = (const float*)d_in[0];
    const float* pc1w = (const float*)d_in[1];
    float* out = (float*)d_out;

    cudaFuncSetAttribute(chamfer_kernel,
                         cudaFuncAttributeMaxDynamicSharedMemorySize,
                         SMEM_BYTES_PAD);

    chamfer_kernel<<<NBLOCKS, TPB, SMEM_BYTES_PAD>>>(pc2, pc1w, out);
}